// round 13
// baseline (speedup 1.0000x reference)
#include <cuda_runtime.h>
#include <cuda_fp16.h>
#include <cstdint>

#define B_   64
#define L_   1024
#define ENC_ 2048
#define DEC_ 512
#define ATT_ 512

// ---------------- scratch (no device-mem allocs allowed) ----------------
__device__ float  g_att2[B_ * ATT_];           // att2 + b_enc + b_dec
__device__ float  g_part[4 * B_ * L_];         // logit partials per N-chunk
__device__ __half g_Wth[ATT_ * ENC_];          // W_enc^T (ATT, ENC) fp16
__device__ __half g_ench[(size_t)B_ * L_ * ENC_];  // enc in fp16 (produced by GEMM)
__device__ int    g_flag[512];                 // per-stripe conversion counters

__device__ __forceinline__ uint32_t pack_h2(float a, float b) {
    __half2 h = __floats2half2_rn(a, b);
    return *reinterpret_cast<uint32_t*>(&h);
}

__global__ void k_dummy() { g_flag[511] += 0; }   // pads GEMM to ncu launch idx 3

// ============================================================
// Transpose W_enc (ENC,ATT) -> g_Wth (ATT,ENC) fp16
// ============================================================
__global__ void k_transpose(const float* __restrict__ We) {
    __shared__ float t[32][33];
    const int k0 = blockIdx.x * 32, n0 = blockIdx.y * 32;
    const int tx = threadIdx.x, ty = threadIdx.y;  // (32, 8)
    #pragma unroll
    for (int j = 0; j < 4; j++)
        t[ty + j * 8][tx] = We[(size_t)(k0 + ty + j * 8) * ATT_ + n0 + tx];
    __syncthreads();
    #pragma unroll
    for (int j = 0; j < 4; j++)
        g_Wth[(size_t)(n0 + ty + j * 8) * ENC_ + k0 + tx] = __float2half_rn(t[tx][ty + j * 8]);
}

// ============================================================
// att2 + zero conversion flags (runs before GEMM every replay)
// ============================================================
__global__ void k_att2(const float* __restrict__ dec, const float* __restrict__ Wd,
                       const float* __restrict__ bd, const float* __restrict__ be) {
    __shared__ float s[DEC_];
    int b = blockIdx.x, a = threadIdx.x;
    if (b == 0) g_flag[a] = 0;                  // 512 threads == 512 flags
    for (int d = threadIdx.x; d < DEC_; d += blockDim.x) s[d] = dec[b * DEC_ + d];
    __syncthreads();
    float acc = bd[a] + be[a];
    #pragma unroll 8
    for (int d = 0; d < DEC_; d++) acc = fmaf(s[d], Wd[d * ATT_ + a], acc);
    g_att2[b * ATT_ + a] = acc;
}

// ============================================================
// Persistent GEMM + fused f32->fp16 conversion.
// grid(4, 74) = 296 CTAs (2/SM, all resident). CTA (nb, by):
//   - converts the nb-quarter (32 rows) of stripe by in prologue,
//     and of stripe by+(j+1)*74 during job j (1 row per k-iter)
//   - group handshake via g_flag[stripe] (4 arrivals)
// CTA tile 128x128, 4 warps, warp 64x64, BK=64 fp16, 3-stage ring.
// ============================================================
#define BK       64
#define KITER    (ENC_ / BK)            // 32
#define A_STG    16384
#define STG      32768
#define NSTAGE   3
#define SMEM_DYN (NSTAGE * STG)         // 98304
#define MSTEP    74

#define CP_ASYNC16(dst, src) \
    asm volatile("cp.async.cg.shared.global [%0], [%1], 16;" :: "r"(dst), "l"(src) : "memory")

#define LDSM4(r, a) \
    asm volatile("ldmatrix.sync.aligned.m8n8.x4.shared.b16 {%0,%1,%2,%3}, [%4];" \
        : "=r"((r)[0]), "=r"((r)[1]), "=r"((r)[2]), "=r"((r)[3]) : "r"(a))

__device__ __forceinline__ uint32_t smem_u32(const void* p) {
    uint32_t a;
    asm("{ .reg .u64 t; cvta.to.shared.u64 t, %1; cvt.u32.u64 %0, t; }" : "=r"(a) : "l"(p));
    return a;
}

__device__ __forceinline__ void mma_f16(float* d, const uint32_t* a, const uint32_t* b) {
    asm volatile(
        "mma.sync.aligned.m16n8k16.row.col.f32.f16.f16.f32 "
        "{%0,%1,%2,%3}, {%4,%5,%6,%7}, {%8,%9}, {%0,%1,%2,%3};"
        : "+f"(d[0]), "+f"(d[1]), "+f"(d[2]), "+f"(d[3])
        : "r"(a[0]), "r"(a[1]), "r"(a[2]), "r"(a[3]), "r"(b[0]), "r"(b[1]));
}

// convert 16 consecutive floats at global element offset `off`
__device__ __forceinline__ void conv16(const float* __restrict__ enc, size_t off) {
    const float4* s4 = (const float4*)(enc + off);
    float4 x0 = s4[0], x1 = s4[1];
    uint4 u0;
    u0.x = pack_h2(x0.x, x0.y);  u0.y = pack_h2(x0.z, x0.w);
    u0.z = pack_h2(x1.x, x1.y);  u0.w = pack_h2(x1.z, x1.w);
    *(uint4*)(g_ench + off) = u0;
    float4 x2 = s4[2], x3 = s4[3];
    uint4 u1;
    u1.x = pack_h2(x2.x, x2.y);  u1.y = pack_h2(x2.z, x2.w);
    u1.z = pack_h2(x3.x, x3.y);  u1.w = pack_h2(x3.z, x3.w);
    *(uint4*)(g_ench + off + 8) = u1;
}

__global__ __launch_bounds__(128, 2) void k_logits_mma(const float* __restrict__ Wf,
                                                       const float* __restrict__ enc) {
    extern __shared__ char dsm[];
    __shared__ float s_c[128], s_w[128];
    __shared__ float ep[2][128];

    const int tid    = threadIdx.x;
    const int nb     = blockIdx.x;               // 0..3
    const int by     = blockIdx.y;               // 0..73
    const int n_base = nb * 128;

    const int wid    = tid >> 5;
    const int lane   = tid & 31;
    const int g      = lane >> 2;
    const int t4     = lane & 3;
    const int warp_m = wid >> 1;
    const int warp_n = wid & 1;
    const int m0     = warp_m * 64;
    const int n0     = warp_n * 64;

    const int hcA = lane >> 4;
    const int rA  = m0 + (lane & 15);
    const int rA7 = rA & 7;
    const int rB  = n0 + ((lane >> 4) << 3) + (lane & 7);
    const int hcB = (lane >> 3) & 1;
    const int rB7 = rB & 7;

    const int njobs = (511 - by) / MSTEP + 1;    // 6 or 7

    s_w[tid] = Wf[n_base + tid];

    const uint32_t smem = smem_u32(dsm);

    auto load_stage = [&](int st, int mbase, int k0f) {
        const uint32_t sb = smem + st * STG;
        #pragma unroll
        for (int it = 0; it < 16; it++) {
            int t = tid + it * 128;
            if (t < 1024) {
                int row = t >> 3, c = t & 7;
                const __half* src = g_ench + (size_t)(mbase + row) * ENC_ + k0f + c * 8;
                CP_ASYNC16(sb + row * 128 + ((c ^ (row & 7)) << 4), src);
            } else {
                int u = t - 1024;
                int n = u >> 3, c = u & 7;
                const __half* src = g_Wth + (size_t)(n_base + n) * ENC_ + k0f + c * 8;
                CP_ASYNC16(sb + A_STG + n * 128 + ((c ^ (n & 7)) << 4), src);
            }
        }
        asm volatile("cp.async.commit_group;" ::: "memory");
    };

    float acc[4][8][4];
    #pragma unroll
    for (int mi = 0; mi < 4; mi++)
        #pragma unroll
        for (int ni = 0; ni < 8; ni++)
            #pragma unroll
            for (int j = 0; j < 4; j++) acc[mi][ni][j] = 0.f;

    uint32_t aF[2][4][4], bF[2][4][4];

    auto load_frags = [&](int buf, uint32_t off, int s) {
        const uint32_t ca = (uint32_t)(((2 * s + hcA) ^ rA7)) << 4;
        #pragma unroll
        for (int mi = 0; mi < 4; mi++)
            LDSM4(aF[buf][mi], off + (uint32_t)(rA + 16 * mi) * 128 + ca);
        const uint32_t cb = (uint32_t)(((2 * s + hcB) ^ rB7)) << 4;
        #pragma unroll
        for (int j = 0; j < 4; j++)
            LDSM4(bF[buf][j], off + A_STG + (uint32_t)(rB + 16 * j) * 128 + cb);
    };

    // ---- prologue: convert this CTA's quarter of stripe `by` (job 0) ----
    {
        const size_t rbase = (size_t)(by * 128 + nb * 32) * ENC_;
        #pragma unroll 2
        for (int r = 0; r < 32; r++)
            conv16(enc, rbase + (size_t)r * ENC_ + tid * 16);
        __threadfence();
        __syncthreads();
        if (tid == 0) atomicAdd(&g_flag[by], 1);
    }

    for (int j = 0; j < njobs; j++) {
        const int stripe = by + j * MSTEP;
        const int m_base = stripe * 128;
        const int b      = m_base / L_;
        const bool more  = (j + 1 < njobs);
        const int snext  = stripe + MSTEP;

        // wait for this stripe's conversion (4 group arrivals)
        if (tid == 0) {
            while (*(volatile int*)&g_flag[stripe] < 4) __nanosleep(64);
        }
        __syncthreads();

        s_c[tid] = g_att2[b * ATT_ + n_base + tid];

        load_stage(0, m_base, 0);
        load_stage(1, m_base, BK);
        asm volatile("cp.async.wait_group 0;" ::: "memory");
        __syncthreads();
        load_frags(0, smem, 0);

        int stage = 0;
        for (int kk = 0; kk < KITER; kk++) {
            const uint32_t off = smem + (uint32_t)stage * STG;
            int nstage = stage + 1; if (nstage == NSTAGE) nstage = 0;

            if (kk + 2 < KITER) {
                int slot = stage + 2; if (slot >= NSTAGE) slot -= NSTAGE;
                load_stage(slot, m_base, (kk + 2) * BK);
            }

            // convert one row of next stripe's quarter (overlapped)
            if (more)
                conv16(enc, (size_t)(snext * 128 + nb * 32 + kk) * ENC_ + tid * 16);

            #pragma unroll
            for (int s = 0; s < 4; s++) {
                if (s < 3) load_frags((s + 1) & 1, off, s + 1);
                const int cb = s & 1;
                #pragma unroll
                for (int mi = 0; mi < 4; mi++)
                    #pragma unroll
                    for (int jj = 0; jj < 4; jj++) {
                        mma_f16(acc[mi][2 * jj],     aF[cb][mi], &bF[cb][jj][0]);
                        mma_f16(acc[mi][2 * jj + 1], aF[cb][mi], &bF[cb][jj][2]);
                    }
            }

            if (kk + 1 < KITER) {
                asm volatile("cp.async.wait_group 0;" ::: "memory");
                __syncthreads();
                if (kk + 2 < KITER) load_frags(0, smem + (uint32_t)nstage * STG, 0);
                else                load_frags(0, smem + (uint32_t)nstage * STG, 0);
            }
            stage = nstage;
        }

        // publish next stripe's conversion AFTER all its rows stored
        if (more) {
            __threadfence();
            __syncthreads();
            if (tid == 0) atomicAdd(&g_flag[snext], 1);
        }

        // ---- epilogue for this job ----
        #pragma unroll
        for (int mi = 0; mi < 4; mi++) {
            float r0s = 0.f, r1s = 0.f;
            #pragma unroll
            for (int ni = 0; ni < 8; ni++) {
                int cc = n0 + ni * 8 + 2 * t4;
                float v;
                v = acc[mi][ni][0] + s_c[cc];     v = fmaxf(v, 0.f); r0s = fmaf(v, s_w[cc], r0s);
                v = acc[mi][ni][1] + s_c[cc + 1]; v = fmaxf(v, 0.f); r0s = fmaf(v, s_w[cc + 1], r0s);
                v = acc[mi][ni][2] + s_c[cc];     v = fmaxf(v, 0.f); r1s = fmaf(v, s_w[cc], r1s);
                v = acc[mi][ni][3] + s_c[cc + 1]; v = fmaxf(v, 0.f); r1s = fmaf(v, s_w[cc + 1], r1s);
                acc[mi][ni][0] = 0.f; acc[mi][ni][1] = 0.f;
                acc[mi][ni][2] = 0.f; acc[mi][ni][3] = 0.f;
            }
            r0s += __shfl_xor_sync(0xffffffffu, r0s, 1);
            r0s += __shfl_xor_sync(0xffffffffu, r0s, 2);
            r1s += __shfl_xor_sync(0xffffffffu, r1s, 1);
            r1s += __shfl_xor_sync(0xffffffffu, r1s, 2);
            if (t4 == 0) {
                ep[warp_n][m0 + mi * 16 + g]     = r0s;
                ep[warp_n][m0 + mi * 16 + 8 + g] = r1s;
            }
        }
        __syncthreads();
        g_part[nb * (B_ * L_) + m_base + tid] = ep[0][tid] + ep[1][tid];
        __syncthreads();   // ep reuse safety for next job
    }
}

// ============================================================
// context + fused softmax (unchanged). grid(8, B_), block(256)
// ============================================================
__global__ __launch_bounds__(256) void k_context(float* __restrict__ out_att,
                                                 float* __restrict__ ctx) {
    const int eb = blockIdx.x;
    const int b  = blockIdx.y;
    const int tid = threadIdx.x;
    const int w  = tid >> 5;
    const int et = tid & 31;

    __shared__ float sa[L_];
    __shared__ float red[8][256];
    __shared__ float rbuf[8];

    float v[4];
    #pragma unroll
    for (int i = 0; i < 4; i++) {
        int l = tid + i * 256;
        float s = 0.f;
        #pragma unroll
        for (int p = 0; p < 4; p++) s += g_part[p * (B_ * L_) + b * L_ + l];
        v[i] = s;
    }
    float mx = fmaxf(fmaxf(v[0], v[1]), fmaxf(v[2], v[3]));
    #pragma unroll
    for (int off = 16; off; off >>= 1) mx = fmaxf(mx, __shfl_xor_sync(0xffffffffu, mx, off));
    if ((tid & 31) == 0) rbuf[tid >> 5] = mx;
    __syncthreads();
    float bm = rbuf[0];
    #pragma unroll
    for (int i = 1; i < 8; i++) bm = fmaxf(bm, rbuf[i]);
    __syncthreads();
    float sum = 0.f;
    #pragma unroll
    for (int i = 0; i < 4; i++) { v[i] = expf(v[i] - bm); sum += v[i]; }
    #pragma unroll
    for (int off = 16; off; off >>= 1) sum += __shfl_xor_sync(0xffffffffu, sum, off);
    if ((tid & 31) == 0) rbuf[tid >> 5] = sum;
    __syncthreads();
    float tot = 0.f;
    #pragma unroll
    for (int i = 0; i < 8; i++) tot += rbuf[i];
    float inv = 1.f / tot;
    #pragma unroll
    for (int i = 0; i < 4; i++) {
        float a = v[i] * inv;
        sa[tid + i * 256] = a;
        if (eb == 0) out_att[b * L_ + tid + i * 256] = a;
    }
    __syncthreads();

    const uint4* base = (const uint4*)(g_ench + (size_t)b * L_ * ENC_) + eb * 32 + et;
    float a[8];
    #pragma unroll
    for (int j = 0; j < 8; j++) a[j] = 0.f;

    const int l0 = w * 128;
    #pragma unroll 4
    for (int t = 0; t < 128; t++) {
        int l = l0 + t;
        uint4 vv = base[(size_t)l * (ENC_ / 8)];
        float wgt = sa[l];
        float2 f;
        f = __half22float2(*(__half2*)&vv.x); a[0] = fmaf(wgt, f.x, a[0]); a[1] = fmaf(wgt, f.y, a[1]);
        f = __half22float2(*(__half2*)&vv.y); a[2] = fmaf(wgt, f.x, a[2]); a[3] = fmaf(wgt, f.y, a[3]);
        f = __half22float2(*(__half2*)&vv.z); a[4] = fmaf(wgt, f.x, a[4]); a[5] = fmaf(wgt, f.y, a[5]);
        f = __half22float2(*(__half2*)&vv.w); a[6] = fmaf(wgt, f.x, a[6]); a[7] = fmaf(wgt, f.y, a[7]);
    }
    #pragma unroll
    for (int j = 0; j < 8; j++) red[w][et * 8 + j] = a[j];
    __syncthreads();

    float s = 0.f;
    #pragma unroll
    for (int w2 = 0; w2 < 8; w2++) s += red[w2][tid];
    ctx[b * ENC_ + eb * 256 + tid] = s;
}

// ============================================================
extern "C" void kernel_launch(void* const* d_in, const int* in_sizes, int n_in,
                              void* d_out, int out_size) {
    const float* enc  = (const float*)d_in[0];
    const float* dech = (const float*)d_in[1];
    const float* We   = (const float*)d_in[2];
    const float* be   = (const float*)d_in[3];
    const float* Wd   = (const float*)d_in[4];
    const float* bd   = (const float*)d_in[5];
    const float* Wf   = (const float*)d_in[6];
    // d_in[7] = b_full: constant logit shift, invariant under softmax -> unused

    float* out_ctx = (float*)d_out;
    float* out_att = (float*)d_out + B_ * ENC_;

    static int smem_set = 0;
    if (!smem_set) {
        cudaFuncSetAttribute(k_logits_mma, cudaFuncAttributeMaxDynamicSharedMemorySize, SMEM_DYN);
        smem_set = 1;
    }

    dim3 gt(ENC_ / 32, ATT_ / 32);
    k_transpose<<<gt, dim3(32, 8)>>>(We);          // idx 0
    k_att2<<<B_, 512>>>(dech, Wd, bd, be);         // idx 1 (also zeroes flags)
    k_dummy<<<1, 1>>>();                            // idx 2
    dim3 g2(4, MSTEP);                              // (4, 74) persistent
    k_logits_mma<<<g2, 128, SMEM_DYN>>>(Wf, enc);  // idx 3 <- profiled
    dim3 g4(8, B_);
    k_context<<<g4, 256>>>(out_att, out_ctx);
}

// round 14
// speedup vs baseline: 1.0749x; 1.0749x over previous
#include <cuda_runtime.h>
#include <cuda_fp16.h>
#include <cstdint>

#define B_   64
#define L_   1024
#define ENC_ 2048
#define DEC_ 512
#define ATT_ 512

// ---------------- scratch (no device-mem allocs allowed) ----------------
__device__ float  g_att2[B_ * ATT_];           // att2 + b_enc + b_dec
__device__ float  g_part[4 * B_ * L_];         // logit partials per N-chunk
__device__ __half g_Wth[ATT_ * ENC_];          // W_enc^T (ATT, ENC) fp16
__device__ __half g_ench[(size_t)B_ * L_ * ENC_];  // enc in fp16 (produced by GEMM)
__device__ int    g_flag[512];                 // per-stripe conversion counters

__device__ __forceinline__ uint32_t pack_h2(float a, float b) {
    __half2 h = __floats2half2_rn(a, b);
    return *reinterpret_cast<uint32_t*>(&h);
}

__global__ void k_dummy() { g_flag[511] += 0; }   // pads GEMM to ncu launch idx 3

// ============================================================
// Transpose W_enc (ENC,ATT) -> g_Wth (ATT,ENC) fp16
// ============================================================
__global__ void k_transpose(const float* __restrict__ We) {
    __shared__ float t[32][33];
    const int k0 = blockIdx.x * 32, n0 = blockIdx.y * 32;
    const int tx = threadIdx.x, ty = threadIdx.y;  // (32, 8)
    #pragma unroll
    for (int j = 0; j < 4; j++)
        t[ty + j * 8][tx] = We[(size_t)(k0 + ty + j * 8) * ATT_ + n0 + tx];
    __syncthreads();
    #pragma unroll
    for (int j = 0; j < 4; j++)
        g_Wth[(size_t)(n0 + ty + j * 8) * ENC_ + k0 + tx] = __float2half_rn(t[tx][ty + j * 8]);
}

// ============================================================
// att2 + zero conversion flags (runs before GEMM every replay)
// ============================================================
__global__ void k_att2(const float* __restrict__ dec, const float* __restrict__ Wd,
                       const float* __restrict__ bd, const float* __restrict__ be) {
    __shared__ float s[DEC_];
    int b = blockIdx.x, a = threadIdx.x;
    if (b == 0) g_flag[a] = 0;
    for (int d = threadIdx.x; d < DEC_; d += blockDim.x) s[d] = dec[b * DEC_ + d];
    __syncthreads();
    float acc = bd[a] + be[a];
    #pragma unroll 8
    for (int d = 0; d < DEC_; d++) acc = fmaf(s[d], Wd[d * ATT_ + a], acc);
    g_att2[b * ATT_ + a] = acc;
}

// ============================================================
// Persistent GEMM + cp.async-staged f32->fp16 conversion.
// grid(4, 74) = 296 CTAs (2/SM, all resident).
// 2-stage main ring (64KB) + 2x8KB f32 conv buffers.
// Per k-iter: commit{main stage kk+1, conv row kk+1}; convert row kk
// from smem; compute kk; wait_group 0 at iter end.
// ============================================================
#define BK       64
#define KITER    (ENC_ / BK)            // 32
#define A_STG    16384
#define STG      32768
#define CONV_OFF (2 * STG)              // 65536
#define SMEM_DYN (2 * STG + 2 * 8192)   // 81920
#define MSTEP    74

#define CP_ASYNC16(dst, src) \
    asm volatile("cp.async.cg.shared.global [%0], [%1], 16;" :: "r"(dst), "l"(src) : "memory")

#define LDSM4(r, a) \
    asm volatile("ldmatrix.sync.aligned.m8n8.x4.shared.b16 {%0,%1,%2,%3}, [%4];" \
        : "=r"((r)[0]), "=r"((r)[1]), "=r"((r)[2]), "=r"((r)[3]) : "r"(a))

__device__ __forceinline__ uint32_t smem_u32(const void* p) {
    uint32_t a;
    asm("{ .reg .u64 t; cvta.to.shared.u64 t, %1; cvt.u32.u64 %0, t; }" : "=r"(a) : "l"(p));
    return a;
}

__device__ __forceinline__ void mma_f16(float* d, const uint32_t* a, const uint32_t* b) {
    asm volatile(
        "mma.sync.aligned.m16n8k16.row.col.f32.f16.f16.f32 "
        "{%0,%1,%2,%3}, {%4,%5,%6,%7}, {%8,%9}, {%0,%1,%2,%3};"
        : "+f"(d[0]), "+f"(d[1]), "+f"(d[2]), "+f"(d[3])
        : "r"(a[0]), "r"(a[1]), "r"(a[2]), "r"(a[3]), "r"(b[0]), "r"(b[1]));
}

// direct gmem f32 -> gmem fp16, 16 elems (prologue burst only)
__device__ __forceinline__ void conv16g(const float* __restrict__ enc, size_t off) {
    const float4* s4 = (const float4*)(enc + off);
    float4 x0 = s4[0], x1 = s4[1];
    uint4 u0;
    u0.x = pack_h2(x0.x, x0.y);  u0.y = pack_h2(x0.z, x0.w);
    u0.z = pack_h2(x1.x, x1.y);  u0.w = pack_h2(x1.z, x1.w);
    *(uint4*)(g_ench + off) = u0;
    float4 x2 = s4[2], x3 = s4[3];
    uint4 u1;
    u1.x = pack_h2(x2.x, x2.y);  u1.y = pack_h2(x2.z, x2.w);
    u1.z = pack_h2(x3.x, x3.y);  u1.w = pack_h2(x3.z, x3.w);
    *(uint4*)(g_ench + off + 8) = u1;
}

__global__ __launch_bounds__(128, 2) void k_logits_mma(const float* __restrict__ Wf,
                                                       const float* __restrict__ enc) {
    extern __shared__ char dsm[];
    __shared__ float s_c[128], s_w[128];
    __shared__ float ep[2][128];

    const int tid    = threadIdx.x;
    const int nb     = blockIdx.x;
    const int by     = blockIdx.y;
    const int n_base = nb * 128;

    const int wid    = tid >> 5;
    const int lane   = tid & 31;
    const int g      = lane >> 2;
    const int t4     = lane & 3;
    const int warp_m = wid >> 1;
    const int warp_n = wid & 1;
    const int m0     = warp_m * 64;
    const int n0     = warp_n * 64;

    const int hcA = lane >> 4;
    const int rA  = m0 + (lane & 15);
    const int rA7 = rA & 7;
    const int rB  = n0 + ((lane >> 4) << 3) + (lane & 7);
    const int hcB = (lane >> 3) & 1;
    const int rB7 = rB & 7;

    const int njobs = (511 - by) / MSTEP + 1;

    s_w[tid] = Wf[n_base + tid];

    const uint32_t smem = smem_u32(dsm);

    auto load_stage = [&](int slot, int mbase, int k0f) {
        const uint32_t sb = smem + slot * STG;
        #pragma unroll
        for (int it = 0; it < 16; it++) {
            int t = tid + it * 128;
            if (t < 1024) {
                int row = t >> 3, c = t & 7;
                const __half* src = g_ench + (size_t)(mbase + row) * ENC_ + k0f + c * 8;
                CP_ASYNC16(sb + row * 128 + ((c ^ (row & 7)) << 4), src);
            } else {
                int u = t - 1024;
                int n = u >> 3, c = u & 7;
                const __half* src = g_Wth + (size_t)(n_base + n) * ENC_ + k0f + c * 8;
                CP_ASYNC16(sb + A_STG + n * 128 + ((c ^ (n & 7)) << 4), src);
            }
        }
    };

    // stage one f32 row (8KB) into conv buffer bufi via cp.async (no regs)
    auto conv_load = [&](int bufi, size_t row_off) {
        const uint32_t d = smem + CONV_OFF + bufi * 8192 + tid * 64;
        const float* s = enc + row_off + tid * 16;
        CP_ASYNC16(d,      s);
        CP_ASYNC16(d + 16, s + 4);
        CP_ASYNC16(d + 32, s + 8);
        CP_ASYNC16(d + 48, s + 12);
    };

    // convert staged row bufi -> g_ench[row_off ..]
    auto conv_store = [&](int bufi, size_t row_off) {
        const float4* sb = (const float4*)(dsm + CONV_OFF + bufi * 8192) + tid * 4;
        float4 x0 = sb[0], x1 = sb[1], x2 = sb[2], x3 = sb[3];
        uint4 u0, u1;
        u0.x = pack_h2(x0.x, x0.y);  u0.y = pack_h2(x0.z, x0.w);
        u0.z = pack_h2(x1.x, x1.y);  u0.w = pack_h2(x1.z, x1.w);
        u1.x = pack_h2(x2.x, x2.y);  u1.y = pack_h2(x2.z, x2.w);
        u1.z = pack_h2(x3.x, x3.y);  u1.w = pack_h2(x3.z, x3.w);
        *(uint4*)(g_ench + row_off + tid * 16)     = u0;
        *(uint4*)(g_ench + row_off + tid * 16 + 8) = u1;
    };

    float acc[4][8][4];
    #pragma unroll
    for (int mi = 0; mi < 4; mi++)
        #pragma unroll
        for (int ni = 0; ni < 8; ni++)
            #pragma unroll
            for (int j = 0; j < 4; j++) acc[mi][ni][j] = 0.f;

    uint32_t aF[2][4][4], bF[2][4][4];

    auto load_frags = [&](int buf, uint32_t off, int s) {
        const uint32_t ca = (uint32_t)(((2 * s + hcA) ^ rA7)) << 4;
        #pragma unroll
        for (int mi = 0; mi < 4; mi++)
            LDSM4(aF[buf][mi], off + (uint32_t)(rA + 16 * mi) * 128 + ca);
        const uint32_t cb = (uint32_t)(((2 * s + hcB) ^ rB7)) << 4;
        #pragma unroll
        for (int j = 0; j < 4; j++)
            LDSM4(bF[buf][j], off + A_STG + (uint32_t)(rB + 16 * j) * 128 + cb);
    };

    // ---- prologue: convert this CTA's quarter of stripe `by` (job 0) ----
    {
        const size_t rbase = (size_t)(by * 128 + nb * 32) * ENC_;
        for (int r = 0; r < 32; r++)
            conv16g(enc, rbase + (size_t)r * ENC_ + tid * 16);
        __threadfence();
        __syncthreads();
        if (tid == 0) atomicAdd(&g_flag[by], 1);
    }

    for (int j = 0; j < njobs; j++) {
        const int stripe = by + j * MSTEP;
        const int m_base = stripe * 128;
        const int b      = m_base / L_;
        const bool more  = (j + 1 < njobs);
        const int snext  = stripe + MSTEP;
        // element offset of conv row r: (snext*128 + nb*32 + r) * ENC_
        const size_t crow0 = (size_t)(snext * 128 + nb * 32) * ENC_;

        if (tid == 0) {
            while (*(volatile int*)&g_flag[stripe] < 4) __nanosleep(64);
        }
        __syncthreads();

        s_c[tid] = g_att2[b * ATT_ + n_base + tid];

        // job prologue: stage 0 + conv row 0, one group
        load_stage(0, m_base, 0);
        if (more) conv_load(0, crow0);
        asm volatile("cp.async.commit_group;" ::: "memory");
        asm volatile("cp.async.wait_group 0;" ::: "memory");
        __syncthreads();
        load_frags(0, smem, 0);

        for (int kk = 0; kk < KITER; kk++) {
            const int slot = kk & 1;
            const uint32_t off = smem + (uint32_t)slot * STG;

            if (kk + 1 < KITER) {
                load_stage(slot ^ 1, m_base, (kk + 1) * BK);
                if (more) conv_load((kk + 1) & 1, crow0 + (size_t)(kk + 1) * ENC_);
                asm volatile("cp.async.commit_group;" ::: "memory");
            }

            // convert row kk (staged last iter / prologue) -> fp16 gmem
            if (more) conv_store(kk & 1, crow0 + (size_t)kk * ENC_);

            #pragma unroll
            for (int s = 0; s < 4; s++) {
                if (s < 3) load_frags((s + 1) & 1, off, s + 1);
                const int cb = s & 1;
                #pragma unroll
                for (int mi = 0; mi < 4; mi++)
                    #pragma unroll
                    for (int jj = 0; jj < 4; jj++) {
                        mma_f16(acc[mi][2 * jj],     aF[cb][mi], &bF[cb][jj][0]);
                        mma_f16(acc[mi][2 * jj + 1], aF[cb][mi], &bF[cb][jj][2]);
                    }
            }

            if (kk + 1 < KITER) {
                asm volatile("cp.async.wait_group 0;" ::: "memory");
                __syncthreads();
                load_frags(0, smem + (uint32_t)((kk + 1) & 1) * STG, 0);
            }
        }

        if (more) {
            __threadfence();
            __syncthreads();
            if (tid == 0) atomicAdd(&g_flag[snext], 1);
        }

        // ---- epilogue for this job ----
        #pragma unroll
        for (int mi = 0; mi < 4; mi++) {
            float r0s = 0.f, r1s = 0.f;
            #pragma unroll
            for (int ni = 0; ni < 8; ni++) {
                int cc = n0 + ni * 8 + 2 * t4;
                float v;
                v = acc[mi][ni][0] + s_c[cc];     v = fmaxf(v, 0.f); r0s = fmaf(v, s_w[cc], r0s);
                v = acc[mi][ni][1] + s_c[cc + 1]; v = fmaxf(v, 0.f); r0s = fmaf(v, s_w[cc + 1], r0s);
                v = acc[mi][ni][2] + s_c[cc];     v = fmaxf(v, 0.f); r1s = fmaf(v, s_w[cc], r1s);
                v = acc[mi][ni][3] + s_c[cc + 1]; v = fmaxf(v, 0.f); r1s = fmaf(v, s_w[cc + 1], r1s);
                acc[mi][ni][0] = 0.f; acc[mi][ni][1] = 0.f;
                acc[mi][ni][2] = 0.f; acc[mi][ni][3] = 0.f;
            }
            r0s += __shfl_xor_sync(0xffffffffu, r0s, 1);
            r0s += __shfl_xor_sync(0xffffffffu, r0s, 2);
            r1s += __shfl_xor_sync(0xffffffffu, r1s, 1);
            r1s += __shfl_xor_sync(0xffffffffu, r1s, 2);
            if (t4 == 0) {
                ep[warp_n][m0 + mi * 16 + g]     = r0s;
                ep[warp_n][m0 + mi * 16 + 8 + g] = r1s;
            }
        }
        __syncthreads();
        g_part[nb * (B_ * L_) + m_base + tid] = ep[0][tid] + ep[1][tid];
        __syncthreads();
    }
}

// ============================================================
// context + fused softmax (unchanged). grid(8, B_), block(256)
// ============================================================
__global__ __launch_bounds__(256) void k_context(float* __restrict__ out_att,
                                                 float* __restrict__ ctx) {
    const int eb = blockIdx.x;
    const int b  = blockIdx.y;
    const int tid = threadIdx.x;
    const int w  = tid >> 5;
    const int et = tid & 31;

    __shared__ float sa[L_];
    __shared__ float red[8][256];
    __shared__ float rbuf[8];

    float v[4];
    #pragma unroll
    for (int i = 0; i < 4; i++) {
        int l = tid + i * 256;
        float s = 0.f;
        #pragma unroll
        for (int p = 0; p < 4; p++) s += g_part[p * (B_ * L_) + b * L_ + l];
        v[i] = s;
    }
    float mx = fmaxf(fmaxf(v[0], v[1]), fmaxf(v[2], v[3]));
    #pragma unroll
    for (int off = 16; off; off >>= 1) mx = fmaxf(mx, __shfl_xor_sync(0xffffffffu, mx, off));
    if ((tid & 31) == 0) rbuf[tid >> 5] = mx;
    __syncthreads();
    float bm = rbuf[0];
    #pragma unroll
    for (int i = 1; i < 8; i++) bm = fmaxf(bm, rbuf[i]);
    __syncthreads();
    float sum = 0.f;
    #pragma unroll
    for (int i = 0; i < 4; i++) { v[i] = expf(v[i] - bm); sum += v[i]; }
    #pragma unroll
    for (int off = 16; off; off >>= 1) sum += __shfl_xor_sync(0xffffffffu, sum, off);
    if ((tid & 31) == 0) rbuf[tid >> 5] = sum;
    __syncthreads();
    float tot = 0.f;
    #pragma unroll
    for (int i = 0; i < 8; i++) tot += rbuf[i];
    float inv = 1.f / tot;
    #pragma unroll
    for (int i = 0; i < 4; i++) {
        float a = v[i] * inv;
        sa[tid + i * 256] = a;
        if (eb == 0) out_att[b * L_ + tid + i * 256] = a;
    }
    __syncthreads();

    const uint4* base = (const uint4*)(g_ench + (size_t)b * L_ * ENC_) + eb * 32 + et;
    float a[8];
    #pragma unroll
    for (int j = 0; j < 8; j++) a[j] = 0.f;

    const int l0 = w * 128;
    #pragma unroll 4
    for (int t = 0; t < 128; t++) {
        int l = l0 + t;
        uint4 vv = base[(size_t)l * (ENC_ / 8)];
        float wgt = sa[l];
        float2 f;
        f = __half22float2(*(__half2*)&vv.x); a[0] = fmaf(wgt, f.x, a[0]); a[1] = fmaf(wgt, f.y, a[1]);
        f = __half22float2(*(__half2*)&vv.y); a[2] = fmaf(wgt, f.x, a[2]); a[3] = fmaf(wgt, f.y, a[3]);
        f = __half22float2(*(__half2*)&vv.z); a[4] = fmaf(wgt, f.x, a[4]); a[5] = fmaf(wgt, f.y, a[5]);
        f = __half22float2(*(__half2*)&vv.w); a[6] = fmaf(wgt, f.x, a[6]); a[7] = fmaf(wgt, f.y, a[7]);
    }
    #pragma unroll
    for (int j = 0; j < 8; j++) red[w][et * 8 + j] = a[j];
    __syncthreads();

    float s = 0.f;
    #pragma unroll
    for (int w2 = 0; w2 < 8; w2++) s += red[w2][tid];
    ctx[b * ENC_ + eb * 256 + tid] = s;
}

// ============================================================
extern "C" void kernel_launch(void* const* d_in, const int* in_sizes, int n_in,
                              void* d_out, int out_size) {
    const float* enc  = (const float*)d_in[0];
    const float* dech = (const float*)d_in[1];
    const float* We   = (const float*)d_in[2];
    const float* be   = (const float*)d_in[3];
    const float* Wd   = (const float*)d_in[4];
    const float* bd   = (const float*)d_in[5];
    const float* Wf   = (const float*)d_in[6];
    // d_in[7] = b_full: constant logit shift, invariant under softmax -> unused

    float* out_ctx = (float*)d_out;
    float* out_att = (float*)d_out + B_ * ENC_;

    static int smem_set = 0;
    if (!smem_set) {
        cudaFuncSetAttribute(k_logits_mma, cudaFuncAttributeMaxDynamicSharedMemorySize, SMEM_DYN);
        smem_set = 1;
    }

    dim3 gt(ENC_ / 32, ATT_ / 32);
    k_transpose<<<gt, dim3(32, 8)>>>(We);          // idx 0
    k_att2<<<B_, 512>>>(dech, Wd, bd, be);         // idx 1 (zeroes flags)
    k_dummy<<<1, 1>>>();                            // idx 2
    dim3 g2(4, MSTEP);                              // (4, 74) persistent
    k_logits_mma<<<g2, 128, SMEM_DYN>>>(Wf, enc);  // idx 3 <- profiled
    dim3 g4(8, B_);
    k_context<<<g4, 256>>>(out_att, out_ctx);
}